// round 1
// baseline (speedup 1.0000x reference)
#include <cuda_runtime.h>

#define NN   100000
#define EE   600000
#define INC  128
#define HH   128
#define CC   47
#define LL   3
#define EPSV 1e-5f

// Scratch (device globals; no allocation allowed)
__device__ float g_h[NN * HH];
__device__ float g_agg[NN * HH];
__device__ float g_cnt[NN];
__device__ float g_inv[NN];

// ---------------------------------------------------------------------------
// zero (float4 grid-stride; n must be multiple of 4)
__global__ void k_zero4(float* __restrict__ p, int n4) {
    int i = blockIdx.x * blockDim.x + threadIdx.x;
    int stride = gridDim.x * blockDim.x;
    float4* p4 = (float4*)p;
    float4 z = make_float4(0.f, 0.f, 0.f, 0.f);
    for (; i < n4; i += stride) p4[i] = z;
}

// ---------------------------------------------------------------------------
// degree count
__global__ void k_count(const int* __restrict__ dst) {
    int e = blockIdx.x * blockDim.x + threadIdx.x;
    if (e < EE) atomicAdd(&g_cnt[dst[e]], 1.0f);
}

__global__ void k_inv() {
    int i = blockIdx.x * blockDim.x + threadIdx.x;
    if (i < NN) g_inv[i] = 1.0f / fmaxf(g_cnt[i], 1.0f);
}

// ---------------------------------------------------------------------------
// scatter: agg[dst] += h[src], one warp per edge, float4 vector red
__global__ void k_scatter(const int* __restrict__ src, const int* __restrict__ dst) {
    long long tid = (long long)blockIdx.x * blockDim.x + threadIdx.x;
    int e = (int)(tid >> 5);
    int lane = (int)(tid & 31);
    if (e >= EE) return;
    int s = src[e];
    int d = dst[e];
    const float4* h4 = (const float4*)g_h;
    float4 v = __ldg(&h4[(long long)s * 32 + lane]);
    float4* a4 = (float4*)g_agg;
    float4* addr = &a4[(long long)d * 32 + lane];
    asm volatile("red.global.add.v4.f32 [%0], {%1,%2,%3,%4};"
                 :: "l"(addr), "f"(v.x), "f"(v.y), "f"(v.z), "f"(v.w)
                 : "memory");
}

// ---------------------------------------------------------------------------
// input GEMM: h = relu(bn(x @ W + b)), K=128, tile 64 rows x 128 cols
// block 256 threads; smem: W[128][128] + A[64][128]  = 96 KB
extern "C" __global__ void __launch_bounds__(256)
k_in_gemm(const float* __restrict__ x, const float* __restrict__ W,
          const float* __restrict__ bias,
          const float* __restrict__ bng, const float* __restrict__ bnb,
          const float* __restrict__ bnm, const float* __restrict__ bnv) {
    extern __shared__ float sm[];
    float* Ws = sm;              // 128*128
    float* As = sm + 128 * 128;  // 64*128
    int tid = threadIdx.x;

    const float4* W4 = (const float4*)W;
    float4* Ws4 = (float4*)Ws;
    for (int i = tid; i < 128 * 32; i += 256) Ws4[i] = W4[i];

    int row0 = blockIdx.x * 64;
    const float4* x4 = (const float4*)x;
    float4* As4 = (float4*)As;
    for (int i = tid; i < 64 * 32; i += 256) {
        int r = i >> 5, c = i & 31;
        int gr = row0 + r;
        As4[i] = (gr < NN) ? __ldg(&x4[(long long)gr * 32 + c])
                           : make_float4(0.f, 0.f, 0.f, 0.f);
    }
    __syncthreads();

    int tx = tid & 31, ty = tid >> 5;
    float acc[8][4];
#pragma unroll
    for (int j = 0; j < 8; j++)
#pragma unroll
        for (int q = 0; q < 4; q++) acc[j][q] = 0.f;

    const float4* Wsv = (const float4*)Ws;
#pragma unroll 4
    for (int k = 0; k < 128; k++) {
        float4 bv = Wsv[k * 32 + tx];
#pragma unroll
        for (int j = 0; j < 8; j++) {
            float a = As[(ty * 8 + j) * 128 + k];
            acc[j][0] = fmaf(a, bv.x, acc[j][0]);
            acc[j][1] = fmaf(a, bv.y, acc[j][1]);
            acc[j][2] = fmaf(a, bv.z, acc[j][2]);
            acc[j][3] = fmaf(a, bv.w, acc[j][3]);
        }
    }

    // epilogue: bias + bn + relu
    float sc[4], sh[4], bs[4];
#pragma unroll
    for (int q = 0; q < 4; q++) {
        int col = tx * 4 + q;
        sc[q] = bng[col] * rsqrtf(bnv[col] + EPSV);
        sh[q] = bnb[col] - bnm[col] * sc[q];
        bs[q] = bias[col];
    }
    float4* h4 = (float4*)g_h;
#pragma unroll
    for (int j = 0; j < 8; j++) {
        int gr = row0 + ty * 8 + j;
        if (gr >= NN) continue;
        float4 o;
        o.x = fmaxf(fmaf(acc[j][0] + bs[0], sc[0], sh[0]), 0.f);
        o.y = fmaxf(fmaf(acc[j][1] + bs[1], sc[1], sh[1]), 0.f);
        o.z = fmaxf(fmaf(acc[j][2] + bs[2], sc[2], sh[2]), 0.f);
        o.w = fmaxf(fmaf(acc[j][3] + bs[3], sc[3], sh[3]), 0.f);
        h4[(long long)gr * 32 + tx] = o;
    }
}

// ---------------------------------------------------------------------------
// layer GEMM: t = relu(bn(agg_mean @ Wl + bl + h @ Wr)); h = h + t   (in-place)
// K=256 concat [agg*inv ; h]; smem: Ws[256][128] (128KB) + As[64][256] (64KB)
extern "C" __global__ void __launch_bounds__(256)
k_layer_gemm(int l, const float* __restrict__ Wl, const float* __restrict__ Wr,
             const float* __restrict__ blv,
             const float* __restrict__ bng, const float* __restrict__ bnb,
             const float* __restrict__ bnm, const float* __restrict__ bnv) {
    extern __shared__ float sm[];
    float* Ws = sm;              // 256*128
    float* As = sm + 256 * 128;  // 64*256
    int tid = threadIdx.x;

    const float4* Wl4 = (const float4*)(Wl + (long long)l * HH * HH);
    const float4* Wr4 = (const float4*)(Wr + (long long)l * HH * HH);
    float4* Ws4 = (float4*)Ws;
    for (int i = tid; i < 128 * 32; i += 256) {
        Ws4[i] = __ldg(&Wl4[i]);
        Ws4[128 * 32 + i] = __ldg(&Wr4[i]);
    }

    int row0 = blockIdx.x * 64;
    const float4* a4 = (const float4*)g_agg;
    const float4* h4 = (const float4*)g_h;
    float4* As4 = (float4*)As;
    for (int i = tid; i < 64 * 32; i += 256) {
        int r = i >> 5, c = i & 31;
        int gr = row0 + r;
        float4 va = make_float4(0.f, 0.f, 0.f, 0.f);
        float4 vh = va;
        if (gr < NN) {
            float inv = g_inv[gr];
            va = a4[(long long)gr * 32 + c];
            va.x *= inv; va.y *= inv; va.z *= inv; va.w *= inv;
            vh = h4[(long long)gr * 32 + c];
        }
        As4[r * 64 + c] = va;         // k in [0,128)
        As4[r * 64 + 32 + c] = vh;    // k in [128,256)
    }
    __syncthreads();

    int tx = tid & 31, ty = tid >> 5;
    float acc[8][4];
#pragma unroll
    for (int j = 0; j < 8; j++)
#pragma unroll
        for (int q = 0; q < 4; q++) acc[j][q] = 0.f;

    const float4* Wsv = (const float4*)Ws;
#pragma unroll 2
    for (int k = 0; k < 256; k++) {
        float4 bv = Wsv[k * 32 + tx];
#pragma unroll
        for (int j = 0; j < 8; j++) {
            float a = As[(ty * 8 + j) * 256 + k];
            acc[j][0] = fmaf(a, bv.x, acc[j][0]);
            acc[j][1] = fmaf(a, bv.y, acc[j][1]);
            acc[j][2] = fmaf(a, bv.z, acc[j][2]);
            acc[j][3] = fmaf(a, bv.w, acc[j][3]);
        }
    }

    const float* blp = blv + l * HH;
    const float* gp = bng + l * HH;
    const float* bp = bnb + l * HH;
    const float* mp = bnm + l * HH;
    const float* vp = bnv + l * HH;
    float sc[4], sh[4], bs[4];
#pragma unroll
    for (int q = 0; q < 4; q++) {
        int col = tx * 4 + q;
        sc[q] = gp[col] * rsqrtf(vp[col] + EPSV);
        sh[q] = bp[col] - mp[col] * sc[q];
        bs[q] = blp[col];
    }
    float4* ho4 = (float4*)g_h;
#pragma unroll
    for (int j = 0; j < 8; j++) {
        int gr = row0 + ty * 8 + j;
        if (gr >= NN) continue;
        int r = ty * 8 + j;
        float4 hold = As4[r * 64 + 32 + tx];  // original h row (in smem)
        float4 o;
        o.x = hold.x + fmaxf(fmaf(acc[j][0] + bs[0], sc[0], sh[0]), 0.f);
        o.y = hold.y + fmaxf(fmaf(acc[j][1] + bs[1], sc[1], sh[1]), 0.f);
        o.z = hold.z + fmaxf(fmaf(acc[j][2] + bs[2], sc[2], sh[2]), 0.f);
        o.w = hold.w + fmaxf(fmaf(acc[j][3] + bs[3], sc[3], sh[3]), 0.f);
        ho4[(long long)gr * 32 + tx] = o;
    }
}

// ---------------------------------------------------------------------------
// output GEMM: out = h @ out_W + out_b   [N,47]
// block (64,4): threadIdx.x = row-in-tile (64 rows), threadIdx.y picks 12 cols
// smem: Ws[128][48] (pad 47->48) + As[64][129] (pad vs bank conflicts)
extern "C" __global__ void __launch_bounds__(256)
k_out_gemm(const float* __restrict__ W, const float* __restrict__ bias,
           float* __restrict__ out) {
    extern __shared__ float sm[];
    float* Ws = sm;             // 128*48
    float* As = sm + 128 * 48;  // 64*129
    int tid = threadIdx.y * 64 + threadIdx.x;

    for (int i = tid; i < 128 * CC; i += 256) {
        int k = i / CC, c = i - k * CC;
        Ws[k * 48 + c] = W[i];
    }
    int row0 = blockIdx.x * 64;
    for (int i = tid; i < 64 * 128; i += 256) {
        int r = i >> 7, c = i & 127;
        int gr = row0 + r;
        As[r * 129 + c] = (gr < NN) ? g_h[(long long)gr * 128 + c] : 0.f;
    }
    __syncthreads();

    int r = threadIdx.x;
    int c0 = threadIdx.y * 12;
    float acc[12];
#pragma unroll
    for (int j = 0; j < 12; j++) acc[j] = 0.f;

#pragma unroll 4
    for (int k = 0; k < 128; k++) {
        float a = As[r * 129 + k];
#pragma unroll
        for (int j = 0; j < 12; j++)
            acc[j] = fmaf(a, Ws[k * 48 + c0 + j], acc[j]);
    }

    int gr = row0 + r;
    if (gr < NN) {
#pragma unroll
        for (int j = 0; j < 12; j++) {
            int col = c0 + j;
            if (col < CC) out[(long long)gr * CC + col] = acc[j] + bias[col];
        }
    }
}

// ---------------------------------------------------------------------------
extern "C" void kernel_launch(void* const* d_in, const int* in_sizes, int n_in,
                              void* d_out, int out_size) {
    const float* x     = (const float*)d_in[0];
    const float* in_W  = (const float*)d_in[1];
    const float* in_b  = (const float*)d_in[2];
    const float* ibn_g = (const float*)d_in[3];
    const float* ibn_b = (const float*)d_in[4];
    const float* ibn_m = (const float*)d_in[5];
    const float* ibn_v = (const float*)d_in[6];
    const float* Wl    = (const float*)d_in[7];
    const float* bl    = (const float*)d_in[8];
    const float* Wr    = (const float*)d_in[9];
    const float* bn_g  = (const float*)d_in[10];
    const float* bn_b  = (const float*)d_in[11];
    const float* bn_m  = (const float*)d_in[12];
    const float* bn_v  = (const float*)d_in[13];
    const float* out_W = (const float*)d_in[14];
    const float* out_b = (const float*)d_in[15];
    const int*   ei    = (const int*)d_in[16];
    const int* src = ei;
    const int* dst = ei + EE;
    float* out = (float*)d_out;

    // opt-in large dynamic smem (idempotent)
    static bool attr_done = false;  // attribute setting is stateless config, not caching of work
    size_t smem_in    = (size_t)(128 * 128 + 64 * 128) * 4;   //  96 KB
    size_t smem_layer = (size_t)(256 * 128 + 64 * 256) * 4;   // 192 KB
    size_t smem_out   = (size_t)(128 * 48 + 64 * 129) * 4;    // ~57 KB
    if (!attr_done) {
        cudaFuncSetAttribute(k_in_gemm, cudaFuncAttributeMaxDynamicSharedMemorySize, (int)smem_in);
        cudaFuncSetAttribute(k_layer_gemm, cudaFuncAttributeMaxDynamicSharedMemorySize, (int)smem_layer);
        cudaFuncSetAttribute(k_out_gemm, cudaFuncAttributeMaxDynamicSharedMemorySize, (int)smem_out);
        attr_done = true;
    }

    float* d_cnt; cudaGetSymbolAddress((void**)&d_cnt, g_cnt);
    float* d_agg; cudaGetSymbolAddress((void**)&d_agg, g_agg);

    int gemm_grid = (NN + 63) / 64;  // 1563

    // degree counts (edge-only; recomputed every call)
    k_zero4<<<256, 256>>>(d_cnt, NN / 4);
    k_count<<<(EE + 255) / 256, 256>>>(dst);
    k_inv<<<(NN + 255) / 256, 256>>>();

    // input transform
    k_in_gemm<<<gemm_grid, 256, smem_in>>>(x, in_W, in_b, ibn_g, ibn_b, ibn_m, ibn_v);

    for (int l = 0; l < LL; l++) {
        k_zero4<<<4096, 256>>>(d_agg, NN * HH / 4);
        long long nthreads = (long long)EE * 32;
        k_scatter<<<(int)((nthreads + 255) / 256), 256>>>(src, dst);
        k_layer_gemm<<<gemm_grid, 256, smem_layer>>>(l, Wl, Wr, bl, bn_g, bn_b, bn_m, bn_v);
    }

    k_out_gemm<<<gemm_grid, dim3(64, 4), smem_out>>>(out_W, out_b, out);
}

// round 2
// speedup vs baseline: 1.0268x; 1.0268x over previous
#include <cuda_runtime.h>

#define NN   100000
#define EE   600000
#define INC  128
#define HH   128
#define CC   47
#define LL   3
#define EPSV 1e-5f

// Scratch (device globals; no allocation allowed)
__device__ float g_h[NN * HH];
__device__ float g_agg[NN * HH];
__device__ float g_cnt[NN];
__device__ float g_inv[NN];

// ---------------------------------------------------------------------------
__global__ void k_zero4(float* __restrict__ p, int n4) {
    int i = blockIdx.x * blockDim.x + threadIdx.x;
    int stride = gridDim.x * blockDim.x;
    float4* p4 = (float4*)p;
    float4 z = make_float4(0.f, 0.f, 0.f, 0.f);
    for (; i < n4; i += stride) p4[i] = z;
}

__global__ void k_count(const int* __restrict__ dst) {
    int e = blockIdx.x * blockDim.x + threadIdx.x;
    if (e < EE) atomicAdd(&g_cnt[dst[e]], 1.0f);
}

__global__ void k_inv() {
    int i = blockIdx.x * blockDim.x + threadIdx.x;
    if (i < NN) g_inv[i] = 1.0f / fmaxf(g_cnt[i], 1.0f);
}

// ---------------------------------------------------------------------------
// scatter: agg[dst] += h[src], one warp per edge, float4 vector red
__global__ void k_scatter(const int* __restrict__ src, const int* __restrict__ dst) {
    long long tid = (long long)blockIdx.x * blockDim.x + threadIdx.x;
    int e = (int)(tid >> 5);
    int lane = (int)(tid & 31);
    if (e >= EE) return;
    int s = src[e];
    int d = dst[e];
    const float4* h4 = (const float4*)g_h;
    float4 v = __ldg(&h4[(long long)s * 32 + lane]);
    float4* a4 = (float4*)g_agg;
    float4* addr = &a4[(long long)d * 32 + lane];
    asm volatile("red.global.add.v4.f32 [%0], {%1,%2,%3,%4};"
                 :: "l"(addr), "f"(v.x), "f"(v.y), "f"(v.z), "f"(v.w)
                 : "memory");
}

// ---------------------------------------------------------------------------
// input GEMM: h = relu(bn(x @ W + b))
// tile 128x128, 256 threads, 8x8 micro-tile, K=128 fully resident
// smem: Ws[128][128] + As[128][128] = 128 KB
extern "C" __global__ void __launch_bounds__(256)
k_in_gemm(const float* __restrict__ x, const float* __restrict__ W,
          const float* __restrict__ bias,
          const float* __restrict__ bng, const float* __restrict__ bnb,
          const float* __restrict__ bnm, const float* __restrict__ bnv) {
    extern __shared__ float sm[];
    float* Ws = sm;              // 128*128
    float* As = sm + 128 * 128;  // 128*128
    int tid = threadIdx.x;

    const float4* W4 = (const float4*)W;
    float4* Ws4 = (float4*)Ws;
    for (int i = tid; i < 128 * 32; i += 256) Ws4[i] = W4[i];

    int row0 = blockIdx.x * 128;
    const float4* x4 = (const float4*)x;
    float4* As4 = (float4*)As;
    for (int i = tid; i < 128 * 32; i += 256) {
        int r = i >> 5, c = i & 31;
        int gr = row0 + r;
        As4[i] = (gr < NN) ? __ldg(&x4[(long long)gr * 32 + c])
                           : make_float4(0.f, 0.f, 0.f, 0.f);
    }
    __syncthreads();

    int tx = tid & 15, ty = tid >> 4;
    int rb = ty * 8, cb = tx * 8;
    float acc[8][8];
#pragma unroll
    for (int j = 0; j < 8; j++)
#pragma unroll
        for (int q = 0; q < 8; q++) acc[j][q] = 0.f;

#pragma unroll 1
    for (int k = 0; k < 128; k += 4) {
        float4 a4[8];
#pragma unroll
        for (int j = 0; j < 8; j++)
            a4[j] = *(const float4*)&As[(rb + j) * 128 + k];
#pragma unroll
        for (int i = 0; i < 4; i++) {
            float4 blo = *(const float4*)&Ws[(k + i) * 128 + cb];
            float4 bhi = *(const float4*)&Ws[(k + i) * 128 + cb + 4];
#pragma unroll
            for (int j = 0; j < 8; j++) {
                float av = ((const float*)&a4[j])[i];
                acc[j][0] = fmaf(av, blo.x, acc[j][0]);
                acc[j][1] = fmaf(av, blo.y, acc[j][1]);
                acc[j][2] = fmaf(av, blo.z, acc[j][2]);
                acc[j][3] = fmaf(av, blo.w, acc[j][3]);
                acc[j][4] = fmaf(av, bhi.x, acc[j][4]);
                acc[j][5] = fmaf(av, bhi.y, acc[j][5]);
                acc[j][6] = fmaf(av, bhi.z, acc[j][6]);
                acc[j][7] = fmaf(av, bhi.w, acc[j][7]);
            }
        }
    }

    float sc[8], sh[8], bs[8];
#pragma unroll
    for (int q = 0; q < 8; q++) {
        int col = cb + q;
        sc[q] = bng[col] * rsqrtf(bnv[col] + EPSV);
        sh[q] = bnb[col] - bnm[col] * sc[q];
        bs[q] = bias[col];
    }
    float4* h4 = (float4*)g_h;
#pragma unroll
    for (int j = 0; j < 8; j++) {
        int gr = row0 + rb + j;
        if (gr >= NN) continue;
        float4 o0, o1;
        o0.x = fmaxf(fmaf(acc[j][0] + bs[0], sc[0], sh[0]), 0.f);
        o0.y = fmaxf(fmaf(acc[j][1] + bs[1], sc[1], sh[1]), 0.f);
        o0.z = fmaxf(fmaf(acc[j][2] + bs[2], sc[2], sh[2]), 0.f);
        o0.w = fmaxf(fmaf(acc[j][3] + bs[3], sc[3], sh[3]), 0.f);
        o1.x = fmaxf(fmaf(acc[j][4] + bs[4], sc[4], sh[4]), 0.f);
        o1.y = fmaxf(fmaf(acc[j][5] + bs[5], sc[5], sh[5]), 0.f);
        o1.z = fmaxf(fmaf(acc[j][6] + bs[6], sc[6], sh[6]), 0.f);
        o1.w = fmaxf(fmaf(acc[j][7] + bs[7], sc[7], sh[7]), 0.f);
        h4[(long long)gr * 32 + (cb >> 2)] = o0;
        h4[(long long)gr * 32 + (cb >> 2) + 1] = o1;
    }
}

// ---------------------------------------------------------------------------
// layer GEMM: t = relu(bn(agg_mean @ Wl + bl + h @ Wr)); h = h + t (in-place)
// K=256 as two 128-chunks (chunk0 = agg*inv, chunk1 = h)
// tile 128x128, 256 threads, 8x8 micro-tile
// smem: Ws[256][128] (128 KB) + As[128][128] (64 KB) = 192 KB
extern "C" __global__ void __launch_bounds__(256)
k_layer_gemm(int l, const float* __restrict__ Wl, const float* __restrict__ Wr,
             const float* __restrict__ blv,
             const float* __restrict__ bng, const float* __restrict__ bnb,
             const float* __restrict__ bnm, const float* __restrict__ bnv) {
    extern __shared__ float sm[];
    float* Ws = sm;              // 256*128
    float* As = sm + 256 * 128;  // 128*128
    int tid = threadIdx.x;

    const float4* Wl4 = (const float4*)(Wl + (long long)l * HH * HH);
    const float4* Wr4 = (const float4*)(Wr + (long long)l * HH * HH);
    float4* Ws4 = (float4*)Ws;
    for (int i = tid; i < 128 * 32; i += 256) {
        Ws4[i] = __ldg(&Wl4[i]);
        Ws4[128 * 32 + i] = __ldg(&Wr4[i]);
    }

    int row0 = blockIdx.x * 128;
    int tx = tid & 15, ty = tid >> 4;
    int rb = ty * 8, cb = tx * 8;
    float acc[8][8];
#pragma unroll
    for (int j = 0; j < 8; j++)
#pragma unroll
        for (int q = 0; q < 8; q++) acc[j][q] = 0.f;

    float4* As4 = (float4*)As;
    const float4* a4g = (const float4*)g_agg;
    const float4* h4g = (const float4*)g_h;

#pragma unroll 1
    for (int kc = 0; kc < 2; kc++) {
        // load chunk
        for (int i = tid; i < 128 * 32; i += 256) {
            int r = i >> 5, c = i & 31;
            int gr = row0 + r;
            float4 v = make_float4(0.f, 0.f, 0.f, 0.f);
            if (gr < NN) {
                if (kc == 0) {
                    float inv = g_inv[gr];
                    v = a4g[(long long)gr * 32 + c];
                    v.x *= inv; v.y *= inv; v.z *= inv; v.w *= inv;
                } else {
                    v = h4g[(long long)gr * 32 + c];
                }
            }
            As4[i] = v;
        }
        __syncthreads();

        const float* Wc = Ws + kc * 128 * 128;
#pragma unroll 1
        for (int k = 0; k < 128; k += 4) {
            float4 a4[8];
#pragma unroll
            for (int j = 0; j < 8; j++)
                a4[j] = *(const float4*)&As[(rb + j) * 128 + k];
#pragma unroll
            for (int i = 0; i < 4; i++) {
                float4 blo = *(const float4*)&Wc[(k + i) * 128 + cb];
                float4 bhi = *(const float4*)&Wc[(k + i) * 128 + cb + 4];
#pragma unroll
                for (int j = 0; j < 8; j++) {
                    float av = ((const float*)&a4[j])[i];
                    acc[j][0] = fmaf(av, blo.x, acc[j][0]);
                    acc[j][1] = fmaf(av, blo.y, acc[j][1]);
                    acc[j][2] = fmaf(av, blo.z, acc[j][2]);
                    acc[j][3] = fmaf(av, blo.w, acc[j][3]);
                    acc[j][4] = fmaf(av, bhi.x, acc[j][4]);
                    acc[j][5] = fmaf(av, bhi.y, acc[j][5]);
                    acc[j][6] = fmaf(av, bhi.z, acc[j][6]);
                    acc[j][7] = fmaf(av, bhi.w, acc[j][7]);
                }
            }
        }
        if (kc == 0) __syncthreads();  // before As is overwritten with h
    }

    const float* blp = blv + l * HH;
    const float* gp = bng + l * HH;
    const float* bp = bnb + l * HH;
    const float* mp = bnm + l * HH;
    const float* vp = bnv + l * HH;
    float sc[8], sh[8], bs[8];
#pragma unroll
    for (int q = 0; q < 8; q++) {
        int col = cb + q;
        sc[q] = gp[col] * rsqrtf(vp[col] + EPSV);
        sh[q] = bp[col] - mp[col] * sc[q];
        bs[q] = blp[col];
    }
    float4* ho4 = (float4*)g_h;
#pragma unroll
    for (int j = 0; j < 8; j++) {
        int gr = row0 + rb + j;
        if (gr >= NN) continue;
        // original h row is still in As (chunk 1); h cols == k-index of chunk1
        float4 hl = *(const float4*)&As[(rb + j) * 128 + cb];
        float4 hh = *(const float4*)&As[(rb + j) * 128 + cb + 4];
        float4 o0, o1;
        o0.x = hl.x + fmaxf(fmaf(acc[j][0] + bs[0], sc[0], sh[0]), 0.f);
        o0.y = hl.y + fmaxf(fmaf(acc[j][1] + bs[1], sc[1], sh[1]), 0.f);
        o0.z = hl.z + fmaxf(fmaf(acc[j][2] + bs[2], sc[2], sh[2]), 0.f);
        o0.w = hl.w + fmaxf(fmaf(acc[j][3] + bs[3], sc[3], sh[3]), 0.f);
        o1.x = hh.x + fmaxf(fmaf(acc[j][4] + bs[4], sc[4], sh[4]), 0.f);
        o1.y = hh.y + fmaxf(fmaf(acc[j][5] + bs[5], sc[5], sh[5]), 0.f);
        o1.z = hh.z + fmaxf(fmaf(acc[j][6] + bs[6], sc[6], sh[6]), 0.f);
        o1.w = hh.w + fmaxf(fmaf(acc[j][7] + bs[7], sc[7], sh[7]), 0.f);
        ho4[(long long)gr * 32 + (cb >> 2)] = o0;
        ho4[(long long)gr * 32 + (cb >> 2) + 1] = o1;
    }
}

// ---------------------------------------------------------------------------
// output GEMM: out = h @ out_W + out_b   [N,47]
extern "C" __global__ void __launch_bounds__(256)
k_out_gemm(const float* __restrict__ W, const float* __restrict__ bias,
           float* __restrict__ out) {
    extern __shared__ float sm[];
    float* Ws = sm;             // 128*48
    float* As = sm + 128 * 48;  // 64*129
    int tid = threadIdx.y * 64 + threadIdx.x;

    for (int i = tid; i < 128 * CC; i += 256) {
        int k = i / CC, c = i - k * CC;
        Ws[k * 48 + c] = W[i];
    }
    int row0 = blockIdx.x * 64;
    for (int i = tid; i < 64 * 128; i += 256) {
        int r = i >> 7, c = i & 127;
        int gr = row0 + r;
        As[r * 129 + c] = (gr < NN) ? g_h[(long long)gr * 128 + c] : 0.f;
    }
    __syncthreads();

    int r = threadIdx.x;
    int c0 = threadIdx.y * 12;
    float acc[12];
#pragma unroll
    for (int j = 0; j < 12; j++) acc[j] = 0.f;

#pragma unroll 4
    for (int k = 0; k < 128; k++) {
        float a = As[r * 129 + k];
#pragma unroll
        for (int j = 0; j < 12; j++)
            acc[j] = fmaf(a, Ws[k * 48 + c0 + j], acc[j]);
    }

    int gr = row0 + r;
    if (gr < NN) {
#pragma unroll
        for (int j = 0; j < 12; j++) {
            int col = c0 + j;
            if (col < CC) out[(long long)gr * CC + col] = acc[j] + bias[col];
        }
    }
}

// ---------------------------------------------------------------------------
extern "C" void kernel_launch(void* const* d_in, const int* in_sizes, int n_in,
                              void* d_out, int out_size) {
    const float* x     = (const float*)d_in[0];
    const float* in_W  = (const float*)d_in[1];
    const float* in_b  = (const float*)d_in[2];
    const float* ibn_g = (const float*)d_in[3];
    const float* ibn_b = (const float*)d_in[4];
    const float* ibn_m = (const float*)d_in[5];
    const float* ibn_v = (const float*)d_in[6];
    const float* Wl    = (const float*)d_in[7];
    const float* bl    = (const float*)d_in[8];
    const float* Wr    = (const float*)d_in[9];
    const float* bn_g  = (const float*)d_in[10];
    const float* bn_b  = (const float*)d_in[11];
    const float* bn_m  = (const float*)d_in[12];
    const float* bn_v  = (const float*)d_in[13];
    const float* out_W = (const float*)d_in[14];
    const float* out_b = (const float*)d_in[15];
    const int*   ei    = (const int*)d_in[16];
    const int* src = ei;
    const int* dst = ei + EE;
    float* out = (float*)d_out;

    static bool attr_done = false;
    size_t smem_in    = (size_t)(128 * 128 + 128 * 128) * 4;  // 128 KB
    size_t smem_layer = (size_t)(256 * 128 + 128 * 128) * 4;  // 192 KB
    size_t smem_out   = (size_t)(128 * 48 + 64 * 129) * 4;
    if (!attr_done) {
        cudaFuncSetAttribute(k_in_gemm, cudaFuncAttributeMaxDynamicSharedMemorySize, (int)smem_in);
        cudaFuncSetAttribute(k_layer_gemm, cudaFuncAttributeMaxDynamicSharedMemorySize, (int)smem_layer);
        cudaFuncSetAttribute(k_out_gemm, cudaFuncAttributeMaxDynamicSharedMemorySize, (int)smem_out);
        attr_done = true;
    }

    float* d_cnt; cudaGetSymbolAddress((void**)&d_cnt, g_cnt);
    float* d_agg; cudaGetSymbolAddress((void**)&d_agg, g_agg);

    int gemm_grid = (NN + 127) / 128;  // 782
    int out_grid  = (NN + 63) / 64;    // 1563

    k_zero4<<<256, 256>>>(d_cnt, NN / 4);
    k_count<<<(EE + 255) / 256, 256>>>(dst);
    k_inv<<<(NN + 255) / 256, 256>>>();

    k_in_gemm<<<gemm_grid, 256, smem_in>>>(x, in_W, in_b, ibn_g, ibn_b, ibn_m, ibn_v);

    for (int l = 0; l < LL; l++) {
        k_zero4<<<4096, 256>>>(d_agg, NN * HH / 4);
        long long nthreads = (long long)EE * 32;
        k_scatter<<<(int)((nthreads + 255) / 256), 256>>>(src, dst);
        k_layer_gemm<<<gemm_grid, 256, smem_layer>>>(l, Wl, Wr, bl, bn_g, bn_b, bn_m, bn_v);
    }

    k_out_gemm<<<out_grid, dim3(64, 4), smem_out>>>(out_W, out_b, out);
}

// round 5
// speedup vs baseline: 1.4084x; 1.3717x over previous
#include <cuda_runtime.h>
#include <cuda_bf16.h>
#include <cstdint>

#define NN   100000
#define EE   600000
#define HH   128
#define CC   47
#define LL   3
#define EPSV 1e-5f

// Scratch (device globals; no allocation allowed)
__device__ float g_h[NN * HH];
__device__ float g_agg[NN * HH];
__device__ float g_cnt[NN];
__device__ float g_inv[NN];

// ---------------------------------------------------------------------------
__device__ __forceinline__ uint32_t smem_u32(const void* p) {
    uint32_t a;
    asm("{ .reg .u64 t; cvta.to.shared.u64 t, %1; cvt.u32.u64 %0, t; }"
        : "=r"(a) : "l"(p));
    return a;
}
__device__ __forceinline__ void ldsm4(uint32_t* r, uint32_t addr) {
    asm volatile("ldmatrix.sync.aligned.m8n8.x4.shared.b16 {%0,%1,%2,%3}, [%4];"
                 : "=r"(r[0]), "=r"(r[1]), "=r"(r[2]), "=r"(r[3]) : "r"(addr));
}
__device__ __forceinline__ void mma16816(float* c, const uint32_t* a, const uint32_t* b) {
    asm volatile(
        "mma.sync.aligned.m16n8k16.row.col.f32.bf16.bf16.f32 "
        "{%0,%1,%2,%3}, {%4,%5,%6,%7}, {%8,%9}, {%0,%1,%2,%3};"
        : "+f"(c[0]), "+f"(c[1]), "+f"(c[2]), "+f"(c[3])
        : "r"(a[0]), "r"(a[1]), "r"(a[2]), "r"(a[3]), "r"(b[0]), "r"(b[1]));
}
// split fp32 -> bf16 hi + bf16 lo(residual)
__device__ __forceinline__ void split1(float x, unsigned short& hi, unsigned short& lo) {
    __nv_bfloat16 h = __float2bfloat16(x);
    float r = x - __bfloat162float(h);
    __nv_bfloat16 l = __float2bfloat16(r);
    hi = __bfloat16_as_ushort(h);
    lo = __bfloat16_as_ushort(l);
}

// ---------------------------------------------------------------------------
__global__ void k_zero4(float* __restrict__ p, int n4) {
    int i = blockIdx.x * blockDim.x + threadIdx.x;
    int stride = gridDim.x * blockDim.x;
    float4* p4 = (float4*)p;
    float4 z = make_float4(0.f, 0.f, 0.f, 0.f);
    for (; i < n4; i += stride) p4[i] = z;
}

__global__ void k_count(const int* __restrict__ dst) {
    int e = blockIdx.x * blockDim.x + threadIdx.x;
    if (e < EE) atomicAdd(&g_cnt[dst[e]], 1.0f);
}

__global__ void k_inv() {
    int i = blockIdx.x * blockDim.x + threadIdx.x;
    if (i < NN) g_inv[i] = 1.0f / fmaxf(g_cnt[i], 1.0f);
}

// scatter: agg[dst] += h[src], one warp per edge, float4 vector red
__global__ void k_scatter(const int* __restrict__ src, const int* __restrict__ dst) {
    long long tid = (long long)blockIdx.x * blockDim.x + threadIdx.x;
    int e = (int)(tid >> 5);
    int lane = (int)(tid & 31);
    if (e >= EE) return;
    int s = src[e];
    int d = dst[e];
    const float4* h4 = (const float4*)g_h;
    float4 v = __ldg(&h4[(long long)s * 32 + lane]);
    float4* a4 = (float4*)g_agg;
    float4* addr = &a4[(long long)d * 32 + lane];
    asm volatile("red.global.add.v4.f32 [%0], {%1,%2,%3,%4};"
                 :: "l"(addr), "f"(v.x), "f"(v.y), "f"(v.z), "f"(v.w)
                 : "memory");
}

// ---------------------------------------------------------------------------
// Tensor-core (mma.sync bf16, 3-term split) input GEMM: h = relu(bn(x@W+b))
// smem: sc[128] sh[128] | Ahi | Alo | Bhi | Blo  (A/B: 128 x 136 bf16)
#define ASTR 136           // bf16 elements per A row (272 B)
#define APLANE (128 * ASTR * 2)
extern "C" __global__ void __launch_bounds__(256)
k_in_mma(const float* __restrict__ x, const float* __restrict__ W,
         const float* __restrict__ bias,
         const float* __restrict__ bng, const float* __restrict__ bnb,
         const float* __restrict__ bnm, const float* __restrict__ bnv) {
    extern __shared__ char sm[];
    float* scp = (float*)sm;
    float* shp = (float*)(sm + 512);
    const uint32_t OFF_AHI = 1024;
    const uint32_t OFF_ALO = OFF_AHI + APLANE;
    const uint32_t OFF_BHI = OFF_ALO + APLANE;
    const uint32_t OFF_BLO = OFF_BHI + APLANE;
    unsigned short* Ahi = (unsigned short*)(sm + OFF_AHI);
    unsigned short* Alo = (unsigned short*)(sm + OFF_ALO);
    unsigned short* Bhi = (unsigned short*)(sm + OFF_BHI);
    unsigned short* Blo = (unsigned short*)(sm + OFF_BLO);
    int tid = threadIdx.x;
    int wid = tid >> 5, lane = tid & 31;
    uint32_t sbase = smem_u32(sm);

    if (tid < 128) {
        int c = tid;
        float s = bng[c] * rsqrtf(bnv[c] + EPSV);
        scp[c] = s;
        shp[c] = bnb[c] - bnm[c] * s + bias[c] * s;
    }

    // B[n][k] = W[k][n]
    for (int i = tid; i < 128 * 64; i += 256) {
        int n = i & 127, kp = i >> 7;
        int k = 2 * kp;
        unsigned short h0, l0, h1, l1;
        split1(__ldg(&W[k * 128 + n]), h0, l0);
        split1(__ldg(&W[(k + 1) * 128 + n]), h1, l1);
        Bhi[n * ASTR + k] = h0; Bhi[n * ASTR + k + 1] = h1;
        Blo[n * ASTR + k] = l0; Blo[n * ASTR + k + 1] = l1;
    }

    // A = x tile (row-major)
    int row0 = blockIdx.x * 128;
    const float4* x4 = (const float4*)x;
    for (int i = tid; i < 128 * 32; i += 256) {
        int r = i >> 5, c4 = i & 31;
        int k = 4 * c4;
        float4 v = make_float4(0.f, 0.f, 0.f, 0.f);
        int gr = row0 + r;
        if (gr < NN) v = __ldg(&x4[(long long)gr * 32 + c4]);
        unsigned short h0, l0, h1, l1, h2, l2, h3, l3;
        split1(v.x, h0, l0); split1(v.y, h1, l1);
        split1(v.z, h2, l2); split1(v.w, h3, l3);
        ushort4 uh = make_ushort4(h0, h1, h2, h3);
        ushort4 ul = make_ushort4(l0, l1, l2, l3);
        *(ushort4*)&Ahi[r * ASTR + k] = uh;
        *(ushort4*)&Alo[r * ASTR + k] = ul;
    }
    __syncthreads();

    // warp tile: 32 rows x 64 cols
    int wm = wid & 3, wn = wid >> 2;
    int mwarp = wm * 32, nwarp = wn * 64;
    float c[2][8][4];
#pragma unroll
    for (int mt = 0; mt < 2; mt++)
#pragma unroll
        for (int nt = 0; nt < 8; nt++)
#pragma unroll
            for (int q = 0; q < 4; q++) c[mt][nt][q] = 0.f;

    uint32_t sAhi = sbase + OFF_AHI, sAlo = sbase + OFF_ALO;
    uint32_t sBhi = sbase + OFF_BHI, sBlo = sbase + OFF_BLO;
    uint32_t a_row = (lane & 15);
    uint32_t a_koff = (lane >> 4) << 3;
    uint32_t b_row = ((lane >> 4) << 3) + (lane & 7);
    uint32_t b_koff = ((lane >> 3) & 1) << 3;

#pragma unroll 1
    for (int k0 = 0; k0 < 128; k0 += 16) {
        uint32_t ah[2][4], al[2][4];
#pragma unroll
        for (int mt = 0; mt < 2; mt++) {
            uint32_t off = (mwarp + mt * 16 + a_row) * (ASTR * 2) + (k0 + a_koff) * 2;
            ldsm4(ah[mt], sAhi + off);
            ldsm4(al[mt], sAlo + off);
        }
        uint32_t bh[8][2], bl[8][2];
#pragma unroll
        for (int g = 0; g < 4; g++) {
            uint32_t off = (nwarp + g * 16 + b_row) * (ASTR * 2) + (k0 + b_koff) * 2;
            uint32_t t[4];
            ldsm4(t, sBhi + off);
            bh[2 * g][0] = t[0]; bh[2 * g][1] = t[1];
            bh[2 * g + 1][0] = t[2]; bh[2 * g + 1][1] = t[3];
            ldsm4(t, sBlo + off);
            bl[2 * g][0] = t[0]; bl[2 * g][1] = t[1];
            bl[2 * g + 1][0] = t[2]; bl[2 * g + 1][1] = t[3];
        }
#pragma unroll
        for (int mt = 0; mt < 2; mt++)
#pragma unroll
            for (int nt = 0; nt < 8; nt++) {
                mma16816(c[mt][nt], ah[mt], bh[nt]);
                mma16816(c[mt][nt], ah[mt], bl[nt]);
                mma16816(c[mt][nt], al[mt], bh[nt]);
            }
    }

    // epilogue
    int rq = lane >> 2, cp = (lane & 3) * 2;
    float2* h2 = (float2*)g_h;
#pragma unroll
    for (int mt = 0; mt < 2; mt++)
#pragma unroll
        for (int nt = 0; nt < 8; nt++) {
            int col = nwarp + nt * 8 + cp;
            float s0 = scp[col], s1 = scp[col + 1];
            float t0 = shp[col], t1 = shp[col + 1];
            int r0g = row0 + mwarp + mt * 16 + rq;
            if (r0g < NN) {
                float2 o;
                o.x = fmaxf(fmaf(c[mt][nt][0], s0, t0), 0.f);
                o.y = fmaxf(fmaf(c[mt][nt][1], s1, t1), 0.f);
                h2[(long long)r0g * 64 + (col >> 1)] = o;
            }
            int r1g = r0g + 8;
            if (r1g < NN) {
                float2 o;
                o.x = fmaxf(fmaf(c[mt][nt][2], s0, t0), 0.f);
                o.y = fmaxf(fmaf(c[mt][nt][3], s1, t1), 0.f);
                h2[(long long)r1g * 64 + (col >> 1)] = o;
            }
        }
}

// ---------------------------------------------------------------------------
// layer GEMM: t = relu(bn([agg_mean|h] @ [Wl;Wr] + bl)); h += t (in-place)
// B: 128 n-rows x 264 k-cols bf16 (hi/lo); A chunks 128x136
#define BSTR 264
#define BPLANE (128 * BSTR * 2)
extern "C" __global__ void __launch_bounds__(256)
k_layer_mma(int l, const float* __restrict__ Wl, const float* __restrict__ Wr,
            const float* __restrict__ blv,
            const float* __restrict__ bng, const float* __restrict__ bnb,
            const float* __restrict__ bnm, const float* __restrict__ bnv) {
    extern __shared__ char sm[];
    float* scp = (float*)sm;
    float* shp = (float*)(sm + 512);
    const uint32_t OFF_AHI = 1024;
    const uint32_t OFF_ALO = OFF_AHI + APLANE;
    const uint32_t OFF_BHI = OFF_ALO + APLANE;
    const uint32_t OFF_BLO = OFF_BHI + BPLANE;
    unsigned short* Ahi = (unsigned short*)(sm + OFF_AHI);
    unsigned short* Alo = (unsigned short*)(sm + OFF_ALO);
    unsigned short* Bhi = (unsigned short*)(sm + OFF_BHI);
    unsigned short* Blo = (unsigned short*)(sm + OFF_BLO);
    int tid = threadIdx.x;
    int wid = tid >> 5, lane = tid & 31;
    uint32_t sbase = smem_u32(sm);

    if (tid < 128) {
        int c = tid;
        float s = bng[l * HH + c] * rsqrtf(bnv[l * HH + c] + EPSV);
        scp[c] = s;
        shp[c] = bnb[l * HH + c] - bnm[l * HH + c] * s + blv[l * HH + c] * s;
    }

    // B[n][k] = Wl[k][n] (k<128), Wr[k-128][n] (k>=128)
    const float* Wlp = Wl + (long long)l * HH * HH;
    const float* Wrp = Wr + (long long)l * HH * HH;
    for (int i = tid; i < 128 * 64; i += 256) {
        int n = i & 127, kp = i >> 7;
        int k = 2 * kp;
        unsigned short h0, l0, h1, l1;
        split1(__ldg(&Wlp[k * 128 + n]), h0, l0);
        split1(__ldg(&Wlp[(k + 1) * 128 + n]), h1, l1);
        Bhi[n * BSTR + k] = h0; Bhi[n * BSTR + k + 1] = h1;
        Blo[n * BSTR + k] = l0; Blo[n * BSTR + k + 1] = l1;
        split1(__ldg(&Wrp[k * 128 + n]), h0, l0);
        split1(__ldg(&Wrp[(k + 1) * 128 + n]), h1, l1);
        Bhi[n * BSTR + 128 + k] = h0; Bhi[n * BSTR + 128 + k + 1] = h1;
        Blo[n * BSTR + 128 + k] = l0; Blo[n * BSTR + 128 + k + 1] = l1;
    }

    int row0 = blockIdx.x * 128;
    int wm = wid & 3, wn = wid >> 2;
    int mwarp = wm * 32, nwarp = wn * 64;
    float c[2][8][4];
#pragma unroll
    for (int mt = 0; mt < 2; mt++)
#pragma unroll
        for (int nt = 0; nt < 8; nt++)
#pragma unroll
            for (int q = 0; q < 4; q++) c[mt][nt][q] = 0.f;

    uint32_t sAhi = sbase + OFF_AHI, sAlo = sbase + OFF_ALO;
    uint32_t sBhi = sbase + OFF_BHI, sBlo = sbase + OFF_BLO;
    uint32_t a_row = (lane & 15);
    uint32_t a_koff = (lane >> 4) << 3;
    uint32_t b_row = ((lane >> 4) << 3) + (lane & 7);
    uint32_t b_koff = ((lane >> 3) & 1) << 3;

    const float4* agg4 = (const float4*)g_agg;
    const float4* h4g = (const float4*)g_h;

#pragma unroll 1
    for (int kc = 0; kc < 2; kc++) {
        if (kc == 1) __syncthreads();  // all mma on chunk0 done before overwrite
        for (int i = tid; i < 128 * 32; i += 256) {
            int r = i >> 5, c4 = i & 31;
            int k = 4 * c4;
            float4 v = make_float4(0.f, 0.f, 0.f, 0.f);
            int gr = row0 + r;
            if (gr < NN) {
                if (kc == 0) {
                    float iv = g_inv[gr];
                    v = agg4[(long long)gr * 32 + c4];
                    v.x *= iv; v.y *= iv; v.z *= iv; v.w *= iv;
                } else {
                    v = h4g[(long long)gr * 32 + c4];
                }
            }
            unsigned short h0, l0, h1, l1, h2, l2, h3, l3;
            split1(v.x, h0, l0); split1(v.y, h1, l1);
            split1(v.z, h2, l2); split1(v.w, h3, l3);
            *(ushort4*)&Ahi[r * ASTR + k] = make_ushort4(h0, h1, h2, h3);
            *(ushort4*)&Alo[r * ASTR + k] = make_ushort4(l0, l1, l2, l3);
        }
        __syncthreads();

#pragma unroll 1
        for (int k0 = 0; k0 < 128; k0 += 16) {
            int kb = kc * 128 + k0;  // B k index
            uint32_t ah[2][4], al[2][4];
#pragma unroll
            for (int mt = 0; mt < 2; mt++) {
                uint32_t off = (mwarp + mt * 16 + a_row) * (ASTR * 2) + (k0 + a_koff) * 2;
                ldsm4(ah[mt], sAhi + off);
                ldsm4(al[mt], sAlo + off);
            }
            uint32_t bh[8][2], bl[8][2];
#pragma unroll
            for (int g = 0; g < 4; g++) {
                uint32_t off = (nwarp + g * 16 + b_row) * (BSTR * 2) + (kb + b_koff) * 2;
                uint32_t t[4];
                ldsm4(t, sBhi + off);
                bh[2 * g][0] = t[0]; bh[2 * g][1] = t[1];
                bh[2 * g + 1][0] = t[2]; bh[2 * g + 1][1] = t[3];
                ldsm4(t, sBlo + off);
                bl[2 * g][0] = t[0]; bl[2 * g][1] = t[1];
                bl[2 * g + 1][0] = t[2]; bl[2 * g + 1][1] = t[3];
            }
#pragma unroll
            for (int mt = 0; mt < 2; mt++)
#pragma unroll
                for (int nt = 0; nt < 8; nt++) {
                    mma16816(c[mt][nt], ah[mt], bh[nt]);
                    mma16816(c[mt][nt], ah[mt], bl[nt]);
                    mma16816(c[mt][nt], al[mt], bh[nt]);
                }
        }
    }

    // epilogue: h += relu(bn(acc))
    int rq = lane >> 2, cp = (lane & 3) * 2;
    float2* h2 = (float2*)g_h;
#pragma unroll
    for (int mt = 0; mt < 2; mt++)
#pragma unroll
        for (int nt = 0; nt < 8; nt++) {
            int col = nwarp + nt * 8 + cp;
            float s0 = scp[col], s1 = scp[col + 1];
            float t0 = shp[col], t1 = shp[col + 1];
            int r0g = row0 + mwarp + mt * 16 + rq;
            if (r0g < NN) {
                long long idx = (long long)r0g * 64 + (col >> 1);
                float2 ho = h2[idx];
                float2 o;
                o.x = ho.x + fmaxf(fmaf(c[mt][nt][0], s0, t0), 0.f);
                o.y = ho.y + fmaxf(fmaf(c[mt][nt][1], s1, t1), 0.f);
                h2[idx] = o;
            }
            int r1g = r0g + 8;
            if (r1g < NN) {
                long long idx = (long long)r1g * 64 + (col >> 1);
                float2 ho = h2[idx];
                float2 o;
                o.x = ho.x + fmaxf(fmaf(c[mt][nt][2], s0, t0), 0.f);
                o.y = ho.y + fmaxf(fmaf(c[mt][nt][3], s1, t1), 0.f);
                h2[idx] = o;
            }
        }
}

// ---------------------------------------------------------------------------
// output GEMM: out = h @ out_W + out_b   [N,47]  (SIMT, small)
extern "C" __global__ void __launch_bounds__(256)
k_out_gemm(const float* __restrict__ W, const float* __restrict__ bias,
           float* __restrict__ out) {
    extern __shared__ float smf[];
    float* Ws = smf;              // 128*48
    float* As = smf + 128 * 48;   // 64*129
    int tid = threadIdx.y * 64 + threadIdx.x;

    for (int i = tid; i < 128 * CC; i += 256) {
        int k = i / CC, c = i - k * CC;
        Ws[k * 48 + c] = W[i];
    }
    int row0 = blockIdx.x * 64;
    for (int i = tid; i < 64 * 128; i += 256) {
        int r = i >> 7, c = i & 127;
        int gr = row0 + r;
        As[r * 129 + c] = (gr < NN) ? g_h[(long long)gr * 128 + c] : 0.f;
    }
    __syncthreads();

    int r = threadIdx.x;
    int c0 = threadIdx.y * 12;
    float acc[12];
#pragma unroll
    for (int j = 0; j < 12; j++) acc[j] = 0.f;

#pragma unroll 4
    for (int k = 0; k < 128; k++) {
        float a = As[r * 129 + k];
#pragma unroll
        for (int j = 0; j < 12; j++)
            acc[j] = fmaf(a, Ws[k * 48 + c0 + j], acc[j]);
    }

    int gr = row0 + r;
    if (gr < NN) {
#pragma unroll
        for (int j = 0; j < 12; j++) {
            int col = c0 + j;
            if (col < CC) out[(long long)gr * CC + col] = acc[j] + bias[col];
        }
    }
}

// ---------------------------------------------------------------------------
extern "C" void kernel_launch(void* const* d_in, const int* in_sizes, int n_in,
                              void* d_out, int out_size) {
    const float* x     = (const float*)d_in[0];
    const float* in_W  = (const float*)d_in[1];
    const float* in_b  = (const float*)d_in[2];
    const float* ibn_g = (const float*)d_in[3];
    const float* ibn_b = (const float*)d_in[4];
    const float* ibn_m = (const float*)d_in[5];
    const float* ibn_v = (const float*)d_in[6];
    const float* Wl    = (const float*)d_in[7];
    const float* bl    = (const float*)d_in[8];
    const float* Wr    = (const float*)d_in[9];
    const float* bn_g  = (const float*)d_in[10];
    const float* bn_b  = (const float*)d_in[11];
    const float* bn_m  = (const float*)d_in[12];
    const float* bn_v  = (const float*)d_in[13];
    const float* out_W = (const float*)d_in[14];
    const float* out_b = (const float*)d_in[15];
    const int*   ei    = (const int*)d_in[16];
    const int* src = ei;
    const int* dst = ei + EE;
    float* out = (float*)d_out;

    static bool attr_done = false;
    size_t smem_in    = 1024 + 4ull * APLANE;               // 1 KB + 4*69.6KB? no: 4 planes of 34816 = 140 KB
    size_t smem_layer = 1024 + 2ull * APLANE + 2ull * BPLANE;
    size_t smem_out   = (size_t)(128 * 48 + 64 * 129) * 4;
    if (!attr_done) {
        cudaFuncSetAttribute(k_in_mma, cudaFuncAttributeMaxDynamicSharedMemorySize, (int)smem_in);
        cudaFuncSetAttribute(k_layer_mma, cudaFuncAttributeMaxDynamicSharedMemorySize, (int)smem_layer);
        cudaFuncSetAttribute(k_out_gemm, cudaFuncAttributeMaxDynamicSharedMemorySize, (int)smem_out);
        attr_done = true;
    }

    float* d_cnt; cudaGetSymbolAddress((void**)&d_cnt, g_cnt);
    float* d_agg; cudaGetSymbolAddress((void**)&d_agg, g_agg);

    int gemm_grid = (NN + 127) / 128;  // 782
    int out_grid  = (NN + 63) / 64;    // 1563

    k_zero4<<<256, 256>>>(d_cnt, NN / 4);
    k_count<<<(EE + 255) / 256, 256>>>(dst);
    k_inv<<<(NN + 255) / 256, 256>>>();

    k_in_mma<<<gemm_grid, 256, smem_in>>>(x, in_W, in_b, ibn_g, ibn_b, ibn_m, ibn_v);

    for (int l = 0; l < LL; l++) {
        k_zero4<<<4096, 256>>>(d_agg, NN * HH / 4);
        long long nthreads = (long long)EE * 32;
        k_scatter<<<(int)((nthreads + 255) / 256), 256>>>(src, dst);
        k_layer_mma<<<gemm_grid, 256, smem_layer>>>(l, Wl, Wr, bl, bn_g, bn_b, bn_m, bn_v);
    }

    k_out_gemm<<<out_grid, dim3(64, 4), smem_out>>>(out_W, out_b, out);
}

// round 6
// speedup vs baseline: 1.6932x; 1.2022x over previous
#include <cuda_runtime.h>
#include <cuda_bf16.h>
#include <cstdint>

#define NN   100000
#define EE   600000
#define HH   128
#define CC   47
#define LL   3
#define EPSV 1e-5f

#define SBS  512
#define SNB  ((NN + SBS - 1) / SBS)   // 196

// Scratch (device globals; no allocation allowed)
__device__ float g_h[NN * HH];
__device__ float g_agg[NN * HH];
__device__ int   g_ideg[NN];
__device__ int   g_rs[NN + 1];
__device__ int   g_bsum[SNB];
__device__ int   g_boff[SNB];
__device__ int   g_cursor[NN];
__device__ int   g_csrc[EE];

// ---------------------------------------------------------------------------
__device__ __forceinline__ uint32_t smem_u32(const void* p) {
    uint32_t a;
    asm("{ .reg .u64 t; cvta.to.shared.u64 t, %1; cvt.u32.u64 %0, t; }"
        : "=r"(a) : "l"(p));
    return a;
}
__device__ __forceinline__ void ldsm4(uint32_t* r, uint32_t addr) {
    asm volatile("ldmatrix.sync.aligned.m8n8.x4.shared.b16 {%0,%1,%2,%3}, [%4];"
                 : "=r"(r[0]), "=r"(r[1]), "=r"(r[2]), "=r"(r[3]) : "r"(addr));
}
__device__ __forceinline__ void mma16816(float* c, const uint32_t* a, const uint32_t* b) {
    asm volatile(
        "mma.sync.aligned.m16n8k16.row.col.f32.bf16.bf16.f32 "
        "{%0,%1,%2,%3}, {%4,%5,%6,%7}, {%8,%9}, {%0,%1,%2,%3};"
        : "+f"(c[0]), "+f"(c[1]), "+f"(c[2]), "+f"(c[3])
        : "r"(a[0]), "r"(a[1]), "r"(a[2]), "r"(a[3]), "r"(b[0]), "r"(b[1]));
}
__device__ __forceinline__ void split1(float x, unsigned short& hi, unsigned short& lo) {
    __nv_bfloat16 h = __float2bfloat16(x);
    float r = x - __bfloat162float(h);
    __nv_bfloat16 l = __float2bfloat16(r);
    hi = __bfloat16_as_ushort(h);
    lo = __bfloat16_as_ushort(l);
}

// ---------------------------------------------------------------------------
// CSR build
__global__ void k_zero_int(int* __restrict__ p, int n) {
    int i = blockIdx.x * blockDim.x + threadIdx.x;
    if (i < n) p[i] = 0;
}

__global__ void k_hist(const int* __restrict__ dst) {
    int e = blockIdx.x * blockDim.x + threadIdx.x;
    if (e < EE) atomicAdd(&g_ideg[dst[e]], 1);
}

__global__ void __launch_bounds__(SBS) k_blocksum() {
    __shared__ int s[SBS];
    int i = blockIdx.x * SBS + threadIdx.x;
    s[threadIdx.x] = (i < NN) ? g_ideg[i] : 0;
    __syncthreads();
    for (int off = SBS / 2; off > 0; off >>= 1) {
        if (threadIdx.x < off) s[threadIdx.x] += s[threadIdx.x + off];
        __syncthreads();
    }
    if (threadIdx.x == 0) g_bsum[blockIdx.x] = s[0];
}

__global__ void __launch_bounds__(256) k_scanb() {
    __shared__ int s[SNB];
    int t = threadIdx.x;
    if (t < SNB) s[t] = g_bsum[t];
    __syncthreads();
    if (t == 0) {
        int acc = 0;
        for (int b = 0; b < SNB; b++) { int v = s[b]; s[b] = acc; acc += v; }
        g_rs[NN] = EE;
    }
    __syncthreads();
    if (t < SNB) g_boff[t] = s[t];
}

__global__ void __launch_bounds__(SBS) k_localscan() {
    __shared__ int s[SBS];
    int i = blockIdx.x * SBS + threadIdx.x;
    int d = (i < NN) ? g_ideg[i] : 0;
    s[threadIdx.x] = d;
    __syncthreads();
    for (int off = 1; off < SBS; off <<= 1) {
        int t = (threadIdx.x >= off) ? s[threadIdx.x - off] : 0;
        __syncthreads();
        s[threadIdx.x] += t;
        __syncthreads();
    }
    if (i < NN) g_rs[i] = g_boff[blockIdx.x] + s[threadIdx.x] - d;
}

__global__ void k_fill(const int* __restrict__ src, const int* __restrict__ dst) {
    int e = blockIdx.x * blockDim.x + threadIdx.x;
    if (e >= EE) return;
    int d = dst[e];
    int pos = g_rs[d] + atomicAdd(&g_cursor[d], 1);
    g_csrc[pos] = src[e];
}

// gather mean: agg[n] = mean of h[src] over in-edges (one warp per node)
__global__ void __launch_bounds__(256) k_gather() {
    int w = (blockIdx.x * blockDim.x + threadIdx.x) >> 5;
    int lane = threadIdx.x & 31;
    if (w >= NN) return;
    int beg = g_rs[w], end = g_rs[w + 1];
    const float4* h4 = (const float4*)g_h;
    float4 acc = make_float4(0.f, 0.f, 0.f, 0.f);
    int j = beg;
    for (; j + 1 < end; j += 2) {
        int s0 = g_csrc[j], s1 = g_csrc[j + 1];
        float4 v0 = __ldg(&h4[(long long)s0 * 32 + lane]);
        float4 v1 = __ldg(&h4[(long long)s1 * 32 + lane]);
        acc.x += v0.x + v1.x; acc.y += v0.y + v1.y;
        acc.z += v0.z + v1.z; acc.w += v0.w + v1.w;
    }
    if (j < end) {
        int s0 = g_csrc[j];
        float4 v0 = __ldg(&h4[(long long)s0 * 32 + lane]);
        acc.x += v0.x; acc.y += v0.y; acc.z += v0.z; acc.w += v0.w;
    }
    float inv = 1.0f / (float)max(end - beg, 1);
    acc.x *= inv; acc.y *= inv; acc.z *= inv; acc.w *= inv;
    ((float4*)g_agg)[(long long)w * 32 + lane] = acc;
}

// ---------------------------------------------------------------------------
// input GEMM (mma.sync bf16 3-term split): h = relu(bn(x@W+b))
// 512 threads, block tile 128x128, warp tile 16x64
#define ASTR 136
#define APLANE (128 * ASTR * 2)
extern "C" __global__ void __launch_bounds__(512)
k_in_mma(const float* __restrict__ x, const float* __restrict__ W,
         const float* __restrict__ bias,
         const float* __restrict__ bng, const float* __restrict__ bnb,
         const float* __restrict__ bnm, const float* __restrict__ bnv) {
    extern __shared__ char sm[];
    float* scp = (float*)sm;
    float* shp = (float*)(sm + 512);
    const uint32_t OFF_AHI = 1024;
    const uint32_t OFF_ALO = OFF_AHI + APLANE;
    const uint32_t OFF_BHI = OFF_ALO + APLANE;
    const uint32_t OFF_BLO = OFF_BHI + APLANE;
    unsigned short* Ahi = (unsigned short*)(sm + OFF_AHI);
    unsigned short* Alo = (unsigned short*)(sm + OFF_ALO);
    unsigned short* Bhi = (unsigned short*)(sm + OFF_BHI);
    unsigned short* Blo = (unsigned short*)(sm + OFF_BLO);
    int tid = threadIdx.x;
    int wid = tid >> 5, lane = tid & 31;
    uint32_t sbase = smem_u32(sm);

    if (tid < 128) {
        int c = tid;
        float s = bng[c] * rsqrtf(bnv[c] + EPSV);
        scp[c] = s;
        shp[c] = bnb[c] - bnm[c] * s + bias[c] * s;
    }

    // B[n][k] = W[k][n]
    for (int i = tid; i < 128 * 64; i += 512) {
        int n = i & 127, kp = i >> 7;
        int k = 2 * kp;
        unsigned short h0, l0, h1, l1;
        split1(__ldg(&W[k * 128 + n]), h0, l0);
        split1(__ldg(&W[(k + 1) * 128 + n]), h1, l1);
        Bhi[n * ASTR + k] = h0; Bhi[n * ASTR + k + 1] = h1;
        Blo[n * ASTR + k] = l0; Blo[n * ASTR + k + 1] = l1;
    }

    int row0 = blockIdx.x * 128;
    const float4* x4 = (const float4*)x;
    for (int i = tid; i < 128 * 32; i += 512) {
        int r = i >> 5, c4 = i & 31;
        int k = 4 * c4;
        float4 v = make_float4(0.f, 0.f, 0.f, 0.f);
        int gr = row0 + r;
        if (gr < NN) v = __ldg(&x4[(long long)gr * 32 + c4]);
        unsigned short h0, l0, h1, l1, h2, l2, h3, l3;
        split1(v.x, h0, l0); split1(v.y, h1, l1);
        split1(v.z, h2, l2); split1(v.w, h3, l3);
        *(ushort4*)&Ahi[r * ASTR + k] = make_ushort4(h0, h1, h2, h3);
        *(ushort4*)&Alo[r * ASTR + k] = make_ushort4(l0, l1, l2, l3);
    }
    __syncthreads();

    int wm = wid & 7, wn = wid >> 3;      // 8 m-groups x 2 n-groups
    int mwarp = wm * 16, nwarp = wn * 64;
    float c[8][4];
#pragma unroll
    for (int nt = 0; nt < 8; nt++)
#pragma unroll
        for (int q = 0; q < 4; q++) c[nt][q] = 0.f;

    uint32_t sAhi = sbase + OFF_AHI, sAlo = sbase + OFF_ALO;
    uint32_t sBhi = sbase + OFF_BHI, sBlo = sbase + OFF_BLO;
    uint32_t a_row = (lane & 15);
    uint32_t a_koff = (lane >> 4) << 3;
    uint32_t b_row = ((lane >> 4) << 3) + (lane & 7);
    uint32_t b_koff = ((lane >> 3) & 1) << 3;

#pragma unroll 1
    for (int k0 = 0; k0 < 128; k0 += 16) {
        uint32_t ah[4], al[4];
        {
            uint32_t off = (mwarp + a_row) * (ASTR * 2) + (k0 + a_koff) * 2;
            ldsm4(ah, sAhi + off);
            ldsm4(al, sAlo + off);
        }
        uint32_t bh[8][2], bl[8][2];
#pragma unroll
        for (int g = 0; g < 4; g++) {
            uint32_t off = (nwarp + g * 16 + b_row) * (ASTR * 2) + (k0 + b_koff) * 2;
            uint32_t t[4];
            ldsm4(t, sBhi + off);
            bh[2 * g][0] = t[0]; bh[2 * g][1] = t[1];
            bh[2 * g + 1][0] = t[2]; bh[2 * g + 1][1] = t[3];
            ldsm4(t, sBlo + off);
            bl[2 * g][0] = t[0]; bl[2 * g][1] = t[1];
            bl[2 * g + 1][0] = t[2]; bl[2 * g + 1][1] = t[3];
        }
#pragma unroll
        for (int nt = 0; nt < 8; nt++) {
            mma16816(c[nt], ah, bh[nt]);
            mma16816(c[nt], ah, bl[nt]);
            mma16816(c[nt], al, bh[nt]);
        }
    }

    int rq = lane >> 2, cp = (lane & 3) * 2;
    float2* h2 = (float2*)g_h;
#pragma unroll
    for (int nt = 0; nt < 8; nt++) {
        int col = nwarp + nt * 8 + cp;
        float s0 = scp[col], s1 = scp[col + 1];
        float t0 = shp[col], t1 = shp[col + 1];
        int r0g = row0 + mwarp + rq;
        if (r0g < NN) {
            float2 o;
            o.x = fmaxf(fmaf(c[nt][0], s0, t0), 0.f);
            o.y = fmaxf(fmaf(c[nt][1], s1, t1), 0.f);
            h2[(long long)r0g * 64 + (col >> 1)] = o;
        }
        int r1g = r0g + 8;
        if (r1g < NN) {
            float2 o;
            o.x = fmaxf(fmaf(c[nt][2], s0, t0), 0.f);
            o.y = fmaxf(fmaf(c[nt][3], s1, t1), 0.f);
            h2[(long long)r1g * 64 + (col >> 1)] = o;
        }
    }
}

// ---------------------------------------------------------------------------
// layer GEMM: t = relu(bn([agg|h] @ [Wl;Wr] + bl)); h += t (in-place)
#define BSTR 264
#define BPLANE (128 * BSTR * 2)
extern "C" __global__ void __launch_bounds__(512)
k_layer_mma(int l, const float* __restrict__ Wl, const float* __restrict__ Wr,
            const float* __restrict__ blv,
            const float* __restrict__ bng, const float* __restrict__ bnb,
            const float* __restrict__ bnm, const float* __restrict__ bnv) {
    extern __shared__ char sm[];
    float* scp = (float*)sm;
    float* shp = (float*)(sm + 512);
    const uint32_t OFF_AHI = 1024;
    const uint32_t OFF_ALO = OFF_AHI + APLANE;
    const uint32_t OFF_BHI = OFF_ALO + APLANE;
    const uint32_t OFF_BLO = OFF_BHI + BPLANE;
    unsigned short* Ahi = (unsigned short*)(sm + OFF_AHI);
    unsigned short* Alo = (unsigned short*)(sm + OFF_ALO);
    unsigned short* Bhi = (unsigned short*)(sm + OFF_BHI);
    unsigned short* Blo = (unsigned short*)(sm + OFF_BLO);
    int tid = threadIdx.x;
    int wid = tid >> 5, lane = tid & 31;
    uint32_t sbase = smem_u32(sm);

    if (tid < 128) {
        int c = tid;
        float s = bng[l * HH + c] * rsqrtf(bnv[l * HH + c] + EPSV);
        scp[c] = s;
        shp[c] = bnb[l * HH + c] - bnm[l * HH + c] * s + blv[l * HH + c] * s;
    }

    const float* Wlp = Wl + (long long)l * HH * HH;
    const float* Wrp = Wr + (long long)l * HH * HH;
    for (int i = tid; i < 128 * 64; i += 512) {
        int n = i & 127, kp = i >> 7;
        int k = 2 * kp;
        unsigned short h0, l0, h1, l1;
        split1(__ldg(&Wlp[k * 128 + n]), h0, l0);
        split1(__ldg(&Wlp[(k + 1) * 128 + n]), h1, l1);
        Bhi[n * BSTR + k] = h0; Bhi[n * BSTR + k + 1] = h1;
        Blo[n * BSTR + k] = l0; Blo[n * BSTR + k + 1] = l1;
        split1(__ldg(&Wrp[k * 128 + n]), h0, l0);
        split1(__ldg(&Wrp[(k + 1) * 128 + n]), h1, l1);
        Bhi[n * BSTR + 128 + k] = h0; Bhi[n * BSTR + 128 + k + 1] = h1;
        Blo[n * BSTR + 128 + k] = l0; Blo[n * BSTR + 128 + k + 1] = l1;
    }

    int row0 = blockIdx.x * 128;
    int wm = wid & 7, wn = wid >> 3;
    int mwarp = wm * 16, nwarp = wn * 64;
    float c[8][4];
#pragma unroll
    for (int nt = 0; nt < 8; nt++)
#pragma unroll
        for (int q = 0; q < 4; q++) c[nt][q] = 0.f;

    uint32_t sAhi = sbase + OFF_AHI, sAlo = sbase + OFF_ALO;
    uint32_t sBhi = sbase + OFF_BHI, sBlo = sbase + OFF_BLO;
    uint32_t a_row = (lane & 15);
    uint32_t a_koff = (lane >> 4) << 3;
    uint32_t b_row = ((lane >> 4) << 3) + (lane & 7);
    uint32_t b_koff = ((lane >> 3) & 1) << 3;

    const float4* agg4 = (const float4*)g_agg;
    const float4* h4g = (const float4*)g_h;

#pragma unroll 1
    for (int kc = 0; kc < 2; kc++) {
        if (kc == 1) __syncthreads();
        for (int i = tid; i < 128 * 32; i += 512) {
            int r = i >> 5, c4 = i & 31;
            int k = 4 * c4;
            float4 v = make_float4(0.f, 0.f, 0.f, 0.f);
            int gr = row0 + r;
            if (gr < NN)
                v = (kc == 0) ? agg4[(long long)gr * 32 + c4]
                              : h4g[(long long)gr * 32 + c4];
            unsigned short h0, l0, h1, l1, h2, l2, h3, l3;
            split1(v.x, h0, l0); split1(v.y, h1, l1);
            split1(v.z, h2, l2); split1(v.w, h3, l3);
            *(ushort4*)&Ahi[r * ASTR + k] = make_ushort4(h0, h1, h2, h3);
            *(ushort4*)&Alo[r * ASTR + k] = make_ushort4(l0, l1, l2, l3);
        }
        __syncthreads();

#pragma unroll 1
        for (int k0 = 0; k0 < 128; k0 += 16) {
            int kb = kc * 128 + k0;
            uint32_t ah[4], al[4];
            {
                uint32_t off = (mwarp + a_row) * (ASTR * 2) + (k0 + a_koff) * 2;
                ldsm4(ah, sAhi + off);
                ldsm4(al, sAlo + off);
            }
            uint32_t bh[8][2], bl[8][2];
#pragma unroll
            for (int g = 0; g < 4; g++) {
                uint32_t off = (nwarp + g * 16 + b_row) * (BSTR * 2) + (kb + b_koff) * 2;
                uint32_t t[4];
                ldsm4(t, sBhi + off);
                bh[2 * g][0] = t[0]; bh[2 * g][1] = t[1];
                bh[2 * g + 1][0] = t[2]; bh[2 * g + 1][1] = t[3];
                ldsm4(t, sBlo + off);
                bl[2 * g][0] = t[0]; bl[2 * g][1] = t[1];
                bl[2 * g + 1][0] = t[2]; bl[2 * g + 1][1] = t[3];
            }
#pragma unroll
            for (int nt = 0; nt < 8; nt++) {
                mma16816(c[nt], ah, bh[nt]);
                mma16816(c[nt], ah, bl[nt]);
                mma16816(c[nt], al, bh[nt]);
            }
        }
    }

    int rq = lane >> 2, cp = (lane & 3) * 2;
    float2* h2 = (float2*)g_h;
#pragma unroll
    for (int nt = 0; nt < 8; nt++) {
        int col = nwarp + nt * 8 + cp;
        float s0 = scp[col], s1 = scp[col + 1];
        float t0 = shp[col], t1 = shp[col + 1];
        int r0g = row0 + mwarp + rq;
        if (r0g < NN) {
            long long idx = (long long)r0g * 64 + (col >> 1);
            float2 ho = h2[idx];
            float2 o;
            o.x = ho.x + fmaxf(fmaf(c[nt][0], s0, t0), 0.f);
            o.y = ho.y + fmaxf(fmaf(c[nt][1], s1, t1), 0.f);
            h2[idx] = o;
        }
        int r1g = r0g + 8;
        if (r1g < NN) {
            long long idx = (long long)r1g * 64 + (col >> 1);
            float2 ho = h2[idx];
            float2 o;
            o.x = ho.x + fmaxf(fmaf(c[nt][2], s0, t0), 0.f);
            o.y = ho.y + fmaxf(fmaf(c[nt][3], s1, t1), 0.f);
            h2[idx] = o;
        }
    }
}

// ---------------------------------------------------------------------------
// output GEMM: out = h @ out_W + out_b   [N,47]  (SIMT, small)
extern "C" __global__ void __launch_bounds__(256)
k_out_gemm(const float* __restrict__ W, const float* __restrict__ bias,
           float* __restrict__ out) {
    extern __shared__ float smf[];
    float* Ws = smf;              // 128*48
    float* As = smf + 128 * 48;   // 64*129
    int tid = threadIdx.y * 64 + threadIdx.x;

    for (int i = tid; i < 128 * CC; i += 256) {
        int k = i / CC, c = i - k * CC;
        Ws[k * 48 + c] = W[i];
    }
    int row0 = blockIdx.x * 64;
    for (int i = tid; i < 64 * 128; i += 256) {
        int r = i >> 7, c = i & 127;
        int gr = row0 + r;
        As[r * 129 + c] = (gr < NN) ? g_h[(long long)gr * 128 + c] : 0.f;
    }
    __syncthreads();

    int r = threadIdx.x;
    int c0 = threadIdx.y * 12;
    float acc[12];
#pragma unroll
    for (int j = 0; j < 12; j++) acc[j] = 0.f;

#pragma unroll 4
    for (int k = 0; k < 128; k++) {
        float a = As[r * 129 + k];
#pragma unroll
        for (int j = 0; j < 12; j++)
            acc[j] = fmaf(a, Ws[k * 48 + c0 + j], acc[j]);
    }

    int gr = row0 + r;
    if (gr < NN) {
#pragma unroll
        for (int j = 0; j < 12; j++) {
            int col = c0 + j;
            if (col < CC) out[(long long)gr * CC + col] = acc[j] + bias[col];
        }
    }
}

// ---------------------------------------------------------------------------
extern "C" void kernel_launch(void* const* d_in, const int* in_sizes, int n_in,
                              void* d_out, int out_size) {
    const float* x     = (const float*)d_in[0];
    const float* in_W  = (const float*)d_in[1];
    const float* in_b  = (const float*)d_in[2];
    const float* ibn_g = (const float*)d_in[3];
    const float* ibn_b = (const float*)d_in[4];
    const float* ibn_m = (const float*)d_in[5];
    const float* ibn_v = (const float*)d_in[6];
    const float* Wl    = (const float*)d_in[7];
    const float* bl    = (const float*)d_in[8];
    const float* Wr    = (const float*)d_in[9];
    const float* bn_g  = (const float*)d_in[10];
    const float* bn_b  = (const float*)d_in[11];
    const float* bn_m  = (const float*)d_in[12];
    const float* bn_v  = (const float*)d_in[13];
    const float* out_W = (const float*)d_in[14];
    const float* out_b = (const float*)d_in[15];
    const int*   ei    = (const int*)d_in[16];
    const int* src = ei;
    const int* dst = ei + EE;
    float* out = (float*)d_out;

    static bool attr_done = false;
    size_t smem_in    = 1024 + 4ull * APLANE;                 // ~137 KB
    size_t smem_layer = 1024 + 2ull * APLANE + 2ull * BPLANE; // ~201 KB
    size_t smem_out   = (size_t)(128 * 48 + 64 * 129) * 4;
    if (!attr_done) {
        cudaFuncSetAttribute(k_in_mma, cudaFuncAttributeMaxDynamicSharedMemorySize, (int)smem_in);
        cudaFuncSetAttribute(k_layer_mma, cudaFuncAttributeMaxDynamicSharedMemorySize, (int)smem_layer);
        cudaFuncSetAttribute(k_out_gemm, cudaFuncAttributeMaxDynamicSharedMemorySize, (int)smem_out);
        attr_done = true;
    }

    int* d_ideg;   cudaGetSymbolAddress((void**)&d_ideg, g_ideg);
    int* d_cursor; cudaGetSymbolAddress((void**)&d_cursor, g_cursor);

    int gemm_grid = (NN + 127) / 128;  // 782
    int out_grid  = (NN + 63) / 64;    // 1563

    // CSR build (recomputed every call; deterministic work)
    k_zero_int<<<(NN + 255) / 256, 256>>>(d_ideg, NN);
    k_zero_int<<<(NN + 255) / 256, 256>>>(d_cursor, NN);
    k_hist<<<(EE + 255) / 256, 256>>>(dst);
    k_blocksum<<<SNB, SBS>>>();
    k_scanb<<<1, 256>>>();
    k_localscan<<<SNB, SBS>>>();
    k_fill<<<(EE + 255) / 256, 256>>>(src, dst);

    k_in_mma<<<gemm_grid, 512, smem_in>>>(x, in_W, in_b, ibn_g, ibn_b, ibn_m, ibn_v);

    for (int l = 0; l < LL; l++) {
        k_gather<<<(NN * 32 + 255) / 256, 256>>>();
        k_layer_mma<<<gemm_grid, 512, smem_layer>>>(l, Wl, Wr, bl, bn_g, bn_b, bn_m, bn_v);
    }

    k_out_gemm<<<out_grid, dim3(64, 4), smem_out>>>(out_W, out_b, out);
}